// round 16
// baseline (speedup 1.0000x reference)
#include <cuda_runtime.h>
#include <cuda_fp16.h>
#include <math_constants.h>

// Problem constants
constexpr int Bb = 4, Ss = 2048, E = 1024, H = 16, D = 64;
constexpr int M = Bb * Ss;          // 8192 rows of (b,s)
constexpr int N_QKV = 3 * E;        // 3072 packed q|k|v output columns
// fold (1/sqrt(D)) * log2(e) into Q so softmax uses exp2
constexpr float CQ = 1.4426950408889634f * 0.125f;

// ---------------- scratch (device globals; no allocations) ----------------
__device__ __align__(16) __half g_X[M * E];            // x in fp16 [M, E]
__device__ __align__(16) __half g_Wqkv[E * N_QKV];     // [E, 3E] packed
__device__ __align__(16) __half g_Wo[E * E];           // [(n*64+h), E]
__device__ __align__(16) __half g_Q[Bb * H * Ss * D];  // [bh][s][d], scaled by CQ
__device__ __align__(16) __half g_K[Bb * H * Ss * D];  // [bh][s][d]
__device__ __align__(16) __half g_V[Bb * H * D * Ss];  // [bh][d][s]  (transposed)
__device__ __align__(16) __half g_A[M * E];            // attention out [M, E]

// ---------------- helpers ----------------
__device__ __forceinline__ unsigned pack2(__half lo, __half hi) {
    __half2 h = __halves2half2(lo, hi);
    return *reinterpret_cast<unsigned*>(&h);
}
__device__ __forceinline__ void mma16816(float c[4], const unsigned a[4], const unsigned b[2]) {
    asm volatile(
        "mma.sync.aligned.m16n8k16.row.col.f32.f16.f16.f32 "
        "{%0,%1,%2,%3},{%4,%5,%6,%7},{%8,%9},{%0,%1,%2,%3};\n"
        : "+f"(c[0]), "+f"(c[1]), "+f"(c[2]), "+f"(c[3])
        : "r"(a[0]), "r"(a[1]), "r"(a[2]), "r"(a[3]), "r"(b[0]), "r"(b[1]));
}

// ---------------- pack kernels ----------------
__global__ void pack_x(const float* __restrict__ x) {
    int i = blockIdx.x * blockDim.x + threadIdx.x;
    if (i < M * E) g_X[i] = __float2half_rn(x[i]);
}
__global__ void pack_wqkv(const float* __restrict__ Wq, const float* __restrict__ Wk,
                          const float* __restrict__ Wv) {
    int i = blockIdx.x * blockDim.x + threadIdx.x;
    if (i >= E * N_QKV) return;
    int e = i / N_QKV, c = i % N_QKV;
    int which = c >> 10, cn = c & 1023;
    int n = cn >> 6, h = cn & 63;
    const float* W = (which == 0) ? Wq : ((which == 1) ? Wk : Wv);
    g_Wqkv[i] = __float2half_rn(W[(n * E + e) * D + h]);
}
__global__ void pack_wo(const float* __restrict__ Wo) {
    int i = blockIdx.x * blockDim.x + threadIdx.x;
    if (i < E * E) g_Wo[i] = __float2half_rn(Wo[i]);  // Wo already [(n,h), e] row-major
}

// ---------------- fused QKV GEMM: [8192,1024] x [1024,3072] ----------------
// BM=128 BN=128 BK=32, 256 threads (8 warps as 2x4), warp tile 64x32
__global__ __launch_bounds__(256) void gemm_qkv(const float* __restrict__ bq,
                                                const float* __restrict__ bk,
                                                const float* __restrict__ bv) {
    constexpr int K = E, Nn = N_QKV;
    __shared__ __half As[128][40];   // pad 8 halfs -> conflict-free A frags
    __shared__ __half Bs[32][136];   // pad 8 halfs
    int tid = threadIdx.x;
    int bn = blockIdx.x, bm = blockIdx.y;
    int wid = tid >> 5, lane = tid & 31;
    int gid = lane >> 2, tg = lane & 3;
    int wm = (wid >> 2) * 64, wn = (wid & 3) * 32;
    float acc[4][4][4] = {};
    const __half* Ag = g_X + (size_t)bm * 128 * K;
    const __half* Bg = g_Wqkv + bn * 128;
    int ar = tid >> 2, ac = (tid & 3) * 8;
    int br = tid >> 4, bc = (tid & 15) * 8;

    for (int kt = 0; kt < K / 32; kt++) {
        *(uint4*)&As[ar][ac]      = *(const uint4*)&Ag[(size_t)ar * K + kt * 32 + ac];
        *(uint4*)&As[ar + 64][ac] = *(const uint4*)&Ag[(size_t)(ar + 64) * K + kt * 32 + ac];
        *(uint4*)&Bs[br][bc]      = *(const uint4*)&Bg[(size_t)(kt * 32 + br) * Nn + bc];
        *(uint4*)&Bs[br + 16][bc] = *(const uint4*)&Bg[(size_t)(kt * 32 + br + 16) * Nn + bc];
        __syncthreads();
#pragma unroll
        for (int ks = 0; ks < 2; ks++) {
            unsigned a[4][4], b[4][2];
#pragma unroll
            for (int mf = 0; mf < 4; mf++) {
                int r = wm + mf * 16 + gid, c = ks * 16 + tg * 2;
                a[mf][0] = *(unsigned*)&As[r][c];
                a[mf][1] = *(unsigned*)&As[r + 8][c];
                a[mf][2] = *(unsigned*)&As[r][c + 8];
                a[mf][3] = *(unsigned*)&As[r + 8][c + 8];
            }
#pragma unroll
            for (int nf = 0; nf < 4; nf++) {
                int c = wn + nf * 8 + gid, k0 = ks * 16 + tg * 2;
                b[nf][0] = pack2(Bs[k0][c], Bs[k0 + 1][c]);
                b[nf][1] = pack2(Bs[k0 + 8][c], Bs[k0 + 9][c]);
            }
#pragma unroll
            for (int mf = 0; mf < 4; mf++)
#pragma unroll
                for (int nf = 0; nf < 4; nf++)
                    mma16816(acc[mf][nf], a[mf], b[nf]);
        }
        __syncthreads();
    }

    // epilogue: scatter to Q (scaled), K, V(transposed) as fp16
#pragma unroll
    for (int mf = 0; mf < 4; mf++) {
#pragma unroll
        for (int nf = 0; nf < 4; nf++) {
            int row0 = bm * 128 + wm + mf * 16 + gid;
            int col = bn * 128 + wn + nf * 8 + tg * 2;
            int which = col >> 10, cn = col & 1023;
            const float* bias = (which == 0) ? bq : ((which == 1) ? bk : bv);
            float b0 = __ldg(&bias[cn]), b1 = __ldg(&bias[cn + 1]);
            int n = cn >> 6, d = cn & 63;
#pragma unroll
            for (int p = 0; p < 2; p++) {
                int r = row0 + p * 8;
                float v0 = acc[mf][nf][p * 2 + 0] + b0;
                float v1 = acc[mf][nf][p * 2 + 1] + b1;
                if (which == 0) { v0 *= CQ; v1 *= CQ; }
                int b = r >> 11, s = r & 2047;
                int bh = b * H + n;
                if (which == 2) {
                    g_V[(size_t)(bh * D + d) * Ss + s]     = __float2half_rn(v0);
                    g_V[(size_t)(bh * D + d + 1) * Ss + s] = __float2half_rn(v1);
                } else {
                    __half* dst = ((which == 0) ? g_Q : g_K) + ((size_t)bh * Ss + s) * D + d;
                    *reinterpret_cast<__half2*>(dst) =
                        __halves2half2(__float2half_rn(v0), __float2half_rn(v1));
                }
            }
        }
    }
}

// ---------------- flash attention (non-causal, full softmax) ----------------
// grid (Ss/128, B*H); 8 warps; each warp owns 16 query rows; key tiles of 64
__global__ __launch_bounds__(256) void flash() {
    __shared__ __half Ks[64][72];  // [key][d], pad -> conflict-free frag loads
    __shared__ __half Vs[64][72];  // [d][key]
    int tid = threadIdx.x;
    int qb = blockIdx.x, bh = blockIdx.y;
    int wid = tid >> 5, lane = tid & 31, gid = lane >> 2, tg = lane & 3;
    int q0 = qb * 128 + wid * 16;
    const __half* Qp = g_Q + (size_t)bh * Ss * D;
    const __half* Kp = g_K + (size_t)bh * Ss * D;
    const __half* Vp = g_V + (size_t)bh * D * Ss;

    // Q fragments (held in registers for the whole CTA lifetime)
    unsigned qa[4][4];
#pragma unroll
    for (int kf = 0; kf < 4; kf++) {
        int c = kf * 16 + tg * 2;
        qa[kf][0] = *(const unsigned*)&Qp[(size_t)(q0 + gid) * D + c];
        qa[kf][1] = *(const unsigned*)&Qp[(size_t)(q0 + gid + 8) * D + c];
        qa[kf][2] = *(const unsigned*)&Qp[(size_t)(q0 + gid) * D + c + 8];
        qa[kf][3] = *(const unsigned*)&Qp[(size_t)(q0 + gid + 8) * D + c + 8];
    }

    float o[8][4] = {};
    float m0 = -CUDART_INF_F, m1 = -CUDART_INF_F, l0 = 0.f, l1 = 0.f;
    int lr = tid >> 3, lc = (tid & 7) * 8;

    for (int kt = 0; kt < Ss / 64; kt++) {
        *(uint4*)&Ks[lr][lc]      = *(const uint4*)&Kp[(size_t)(kt * 64 + lr) * D + lc];
        *(uint4*)&Ks[lr + 32][lc] = *(const uint4*)&Kp[(size_t)(kt * 64 + lr + 32) * D + lc];
        *(uint4*)&Vs[lr][lc]      = *(const uint4*)&Vp[(size_t)lr * Ss + kt * 64 + lc];
        *(uint4*)&Vs[lr + 32][lc] = *(const uint4*)&Vp[(size_t)(lr + 32) * Ss + kt * 64 + lc];
        __syncthreads();

        // S = Q @ K^T  (already includes 1/sqrt(D)*log2e via Q scaling)
        float s[8][4] = {};
#pragma unroll
        for (int kf = 0; kf < 4; kf++)
#pragma unroll
            for (int nf = 0; nf < 8; nf++) {
                unsigned b2[2];
                b2[0] = *(unsigned*)&Ks[nf * 8 + gid][kf * 16 + tg * 2];
                b2[1] = *(unsigned*)&Ks[nf * 8 + gid][kf * 16 + tg * 2 + 8];
                mma16816(s[nf], qa[kf], b2);
            }

        // online softmax (rows gid and gid+8; quad = lanes {xor 1, xor 2})
        float tm0 = -CUDART_INF_F, tm1 = -CUDART_INF_F;
#pragma unroll
        for (int nf = 0; nf < 8; nf++) {
            tm0 = fmaxf(tm0, fmaxf(s[nf][0], s[nf][1]));
            tm1 = fmaxf(tm1, fmaxf(s[nf][2], s[nf][3]));
        }
        tm0 = fmaxf(tm0, __shfl_xor_sync(0xffffffffu, tm0, 1));
        tm0 = fmaxf(tm0, __shfl_xor_sync(0xffffffffu, tm0, 2));
        tm1 = fmaxf(tm1, __shfl_xor_sync(0xffffffffu, tm1, 1));
        tm1 = fmaxf(tm1, __shfl_xor_sync(0xffffffffu, tm1, 2));
        float nm0 = fmaxf(m0, tm0), nm1 = fmaxf(m1, tm1);
        float cc0 = exp2f(m0 - nm0), cc1 = exp2f(m1 - nm1);
        m0 = nm0; m1 = nm1;
        float ps0 = 0.f, ps1 = 0.f;
#pragma unroll
        for (int nf = 0; nf < 8; nf++) {
            s[nf][0] = exp2f(s[nf][0] - nm0);
            s[nf][1] = exp2f(s[nf][1] - nm0);
            s[nf][2] = exp2f(s[nf][2] - nm1);
            s[nf][3] = exp2f(s[nf][3] - nm1);
            ps0 += s[nf][0] + s[nf][1];
            ps1 += s[nf][2] + s[nf][3];
        }
        l0 = l0 * cc0 + ps0;
        l1 = l1 * cc1 + ps1;
#pragma unroll
        for (int nf = 0; nf < 8; nf++) {
            o[nf][0] *= cc0; o[nf][1] *= cc0;
            o[nf][2] *= cc1; o[nf][3] *= cc1;
        }

        // P (C-fragment layout) -> A fragments directly in registers
        unsigned pa[4][4];
#pragma unroll
        for (int kb = 0; kb < 4; kb++) {
            pa[kb][0] = pack2(__float2half_rn(s[2 * kb][0]), __float2half_rn(s[2 * kb][1]));
            pa[kb][1] = pack2(__float2half_rn(s[2 * kb][2]), __float2half_rn(s[2 * kb][3]));
            pa[kb][2] = pack2(__float2half_rn(s[2 * kb + 1][0]), __float2half_rn(s[2 * kb + 1][1]));
            pa[kb][3] = pack2(__float2half_rn(s[2 * kb + 1][2]), __float2half_rn(s[2 * kb + 1][3]));
        }

        // O += P @ V
#pragma unroll
        for (int kb = 0; kb < 4; kb++)
#pragma unroll
            for (int nf = 0; nf < 8; nf++) {
                unsigned b2[2];
                b2[0] = *(unsigned*)&Vs[nf * 8 + gid][kb * 16 + tg * 2];
                b2[1] = *(unsigned*)&Vs[nf * 8 + gid][kb * 16 + tg * 2 + 8];
                mma16816(o[nf], pa[kb], b2);
            }
        __syncthreads();
    }

    // finalize: divide by row sums, write fp16 to g_A [b*S+s][h*64+d]
    l0 += __shfl_xor_sync(0xffffffffu, l0, 1);
    l0 += __shfl_xor_sync(0xffffffffu, l0, 2);
    l1 += __shfl_xor_sync(0xffffffffu, l1, 1);
    l1 += __shfl_xor_sync(0xffffffffu, l1, 2);
    float i0 = 1.f / l0, i1 = 1.f / l1;
    int b = bh >> 4, hh = bh & 15;
    int s0 = q0 + gid;
#pragma unroll
    for (int nf = 0; nf < 8; nf++) {
        int col = hh * 64 + nf * 8 + tg * 2;
        *(__half2*)&g_A[(size_t)(b * Ss + s0) * E + col] =
            __halves2half2(__float2half_rn(o[nf][0] * i0), __float2half_rn(o[nf][1] * i0));
        *(__half2*)&g_A[(size_t)(b * Ss + s0 + 8) * E + col] =
            __halves2half2(__float2half_rn(o[nf][2] * i1), __float2half_rn(o[nf][3] * i1));
    }
}

// ---------------- output projection: [8192,1024] x [1024,1024] + bo ----------------
__global__ __launch_bounds__(256) void gemm_o(const float* __restrict__ bo,
                                              float* __restrict__ out) {
    constexpr int K = E, Nn = E;
    __shared__ __half As[128][40];
    __shared__ __half Bs[32][136];
    int tid = threadIdx.x;
    int bn = blockIdx.x, bm = blockIdx.y;
    int wid = tid >> 5, lane = tid & 31;
    int gid = lane >> 2, tg = lane & 3;
    int wm = (wid >> 2) * 64, wn = (wid & 3) * 32;
    float acc[4][4][4] = {};
    const __half* Ag = g_A + (size_t)bm * 128 * K;
    const __half* Bg = g_Wo + bn * 128;
    int ar = tid >> 2, ac = (tid & 3) * 8;
    int br = tid >> 4, bc = (tid & 15) * 8;

    for (int kt = 0; kt < K / 32; kt++) {
        *(uint4*)&As[ar][ac]      = *(const uint4*)&Ag[(size_t)ar * K + kt * 32 + ac];
        *(uint4*)&As[ar + 64][ac] = *(const uint4*)&Ag[(size_t)(ar + 64) * K + kt * 32 + ac];
        *(uint4*)&Bs[br][bc]      = *(const uint4*)&Bg[(size_t)(kt * 32 + br) * Nn + bc];
        *(uint4*)&Bs[br + 16][bc] = *(const uint4*)&Bg[(size_t)(kt * 32 + br + 16) * Nn + bc];
        __syncthreads();
#pragma unroll
        for (int ks = 0; ks < 2; ks++) {
            unsigned a[4][4], b[4][2];
#pragma unroll
            for (int mf = 0; mf < 4; mf++) {
                int r = wm + mf * 16 + gid, c = ks * 16 + tg * 2;
                a[mf][0] = *(unsigned*)&As[r][c];
                a[mf][1] = *(unsigned*)&As[r + 8][c];
                a[mf][2] = *(unsigned*)&As[r][c + 8];
                a[mf][3] = *(unsigned*)&As[r + 8][c + 8];
            }
#pragma unroll
            for (int nf = 0; nf < 4; nf++) {
                int c = wn + nf * 8 + gid, k0 = ks * 16 + tg * 2;
                b[nf][0] = pack2(Bs[k0][c], Bs[k0 + 1][c]);
                b[nf][1] = pack2(Bs[k0 + 8][c], Bs[k0 + 9][c]);
            }
#pragma unroll
            for (int mf = 0; mf < 4; mf++)
#pragma unroll
                for (int nf = 0; nf < 4; nf++)
                    mma16816(acc[mf][nf], a[mf], b[nf]);
        }
        __syncthreads();
    }

#pragma unroll
    for (int mf = 0; mf < 4; mf++) {
#pragma unroll
        for (int nf = 0; nf < 4; nf++) {
            int row0 = bm * 128 + wm + mf * 16 + gid;
            int col = bn * 128 + wn + nf * 8 + tg * 2;
            float b0 = __ldg(&bo[col]), b1 = __ldg(&bo[col + 1]);
            *(float2*)&out[(size_t)row0 * E + col] =
                make_float2(acc[mf][nf][0] + b0, acc[mf][nf][1] + b1);
            *(float2*)&out[(size_t)(row0 + 8) * E + col] =
                make_float2(acc[mf][nf][2] + b0, acc[mf][nf][3] + b1);
        }
    }
}

// ---------------- launch ----------------
extern "C" void kernel_launch(void* const* d_in, const int* in_sizes, int n_in,
                              void* d_out, int out_size) {
    const float* x  = (const float*)d_in[0];
    const float* Wq = (const float*)d_in[1];
    const float* bq = (const float*)d_in[2];
    const float* Wk = (const float*)d_in[3];
    const float* bk = (const float*)d_in[4];
    const float* Wv = (const float*)d_in[5];
    const float* bv = (const float*)d_in[6];
    const float* Wo = (const float*)d_in[7];
    const float* bo = (const float*)d_in[8];
    float* out = (float*)d_out;

    pack_x<<<(M * E) / 256, 256>>>(x);
    pack_wqkv<<<(E * N_QKV) / 256, 256>>>(Wq, Wk, Wv);
    pack_wo<<<(E * E) / 256, 256>>>(Wo);
    gemm_qkv<<<dim3(N_QKV / 128, M / 128), 256>>>(bq, bk, bv);
    flash<<<dim3(Ss / 128, Bb * H), 256>>>();
    gemm_o<<<dim3(E / 128, M / 128), 256>>>(bo, out);
}

// round 17
// speedup vs baseline: 1.0033x; 1.0033x over previous
#include <cuda_runtime.h>
#include <cuda_fp16.h>
#include <math_constants.h>

// Problem constants
constexpr int Bb = 4, Ss = 2048, E = 1024, H = 16, D = 64;
constexpr int M = Bb * Ss;          // 8192 rows of (b,s)
constexpr int N_QKV = 3 * E;        // 3072 packed q|k|v output columns
// fold (1/sqrt(D)) * log2(e) into Q so softmax uses exp2
constexpr float CQ = 1.4426950408889634f * 0.125f;

// ---------------- scratch (device globals; no allocations) ----------------
__device__ __align__(16) __half g_X[M * E];            // x in fp16 [M, E]
__device__ __align__(16) __half g_Wqkv[E * N_QKV];     // [E, 3E] packed
__device__ __align__(16) __half g_Wo[E * E];           // [(n*64+h), E]
__device__ __align__(16) __half g_Q[Bb * H * Ss * D];  // [bh][s][d], scaled by CQ
__device__ __align__(16) __half g_K[Bb * H * Ss * D];  // [bh][s][d]
__device__ __align__(16) __half g_V[Bb * H * D * Ss];  // [bh][d][s]  (transposed)
__device__ __align__(16) __half g_A[M * E];            // attention out [M, E]

// ---------------- helpers ----------------
__device__ __forceinline__ unsigned pack2(__half lo, __half hi) {
    __half2 h = __halves2half2(lo, hi);
    return *reinterpret_cast<unsigned*>(&h);
}
__device__ __forceinline__ void mma16816(float c[4], const unsigned a[4], const unsigned b[2]) {
    asm volatile(
        "mma.sync.aligned.m16n8k16.row.col.f32.f16.f16.f32 "
        "{%0,%1,%2,%3},{%4,%5,%6,%7},{%8,%9},{%0,%1,%2,%3};\n"
        : "+f"(c[0]), "+f"(c[1]), "+f"(c[2]), "+f"(c[3])
        : "r"(a[0]), "r"(a[1]), "r"(a[2]), "r"(a[3]), "r"(b[0]), "r"(b[1]));
}

// ---------------- pack kernels ----------------
__global__ void pack_x(const float* __restrict__ x) {
    int i = blockIdx.x * blockDim.x + threadIdx.x;
    if (i < M * E) g_X[i] = __float2half_rn(x[i]);
}
__global__ void pack_wqkv(const float* __restrict__ Wq, const float* __restrict__ Wk,
                          const float* __restrict__ Wv) {
    int i = blockIdx.x * blockDim.x + threadIdx.x;
    if (i >= E * N_QKV) return;
    int e = i / N_QKV, c = i % N_QKV;
    int which = c >> 10, cn = c & 1023;
    int n = cn >> 6, h = cn & 63;
    const float* W = (which == 0) ? Wq : ((which == 1) ? Wk : Wv);
    g_Wqkv[i] = __float2half_rn(W[(n * E + e) * D + h]);
}
__global__ void pack_wo(const float* __restrict__ Wo) {
    int i = blockIdx.x * blockDim.x + threadIdx.x;
    if (i < E * E) g_Wo[i] = __float2half_rn(Wo[i]);  // Wo already [(n,h), e] row-major
}

// ---------------- fused QKV GEMM: [8192,1024] x [1024,3072] ----------------
// BM=128 BN=128 BK=32, 256 threads (8 warps as 2x4), warp tile 64x32
__global__ __launch_bounds__(256) void gemm_qkv(const float* __restrict__ bq,
                                                const float* __restrict__ bk,
                                                const float* __restrict__ bv) {
    constexpr int K = E, Nn = N_QKV;
    __shared__ __half As[128][40];   // pad 8 halfs -> conflict-free A frags
    __shared__ __half Bs[32][136];   // pad 8 halfs
    int tid = threadIdx.x;
    int bn = blockIdx.x, bm = blockIdx.y;
    int wid = tid >> 5, lane = tid & 31;
    int gid = lane >> 2, tg = lane & 3;
    int wm = (wid >> 2) * 64, wn = (wid & 3) * 32;
    float acc[4][4][4] = {};
    const __half* Ag = g_X + (size_t)bm * 128 * K;
    const __half* Bg = g_Wqkv + bn * 128;
    int ar = tid >> 2, ac = (tid & 3) * 8;
    int br = tid >> 4, bc = (tid & 15) * 8;

    for (int kt = 0; kt < K / 32; kt++) {
        *(uint4*)&As[ar][ac]      = *(const uint4*)&Ag[(size_t)ar * K + kt * 32 + ac];
        *(uint4*)&As[ar + 64][ac] = *(const uint4*)&Ag[(size_t)(ar + 64) * K + kt * 32 + ac];
        *(uint4*)&Bs[br][bc]      = *(const uint4*)&Bg[(size_t)(kt * 32 + br) * Nn + bc];
        *(uint4*)&Bs[br + 16][bc] = *(const uint4*)&Bg[(size_t)(kt * 32 + br + 16) * Nn + bc];
        __syncthreads();
#pragma unroll
        for (int ks = 0; ks < 2; ks++) {
            unsigned a[4][4], b[4][2];
#pragma unroll
            for (int mf = 0; mf < 4; mf++) {
                int r = wm + mf * 16 + gid, c = ks * 16 + tg * 2;
                a[mf][0] = *(unsigned*)&As[r][c];
                a[mf][1] = *(unsigned*)&As[r + 8][c];
                a[mf][2] = *(unsigned*)&As[r][c + 8];
                a[mf][3] = *(unsigned*)&As[r + 8][c + 8];
            }
#pragma unroll
            for (int nf = 0; nf < 4; nf++) {
                int c = wn + nf * 8 + gid, k0 = ks * 16 + tg * 2;
                b[nf][0] = pack2(Bs[k0][c], Bs[k0 + 1][c]);
                b[nf][1] = pack2(Bs[k0 + 8][c], Bs[k0 + 9][c]);
            }
#pragma unroll
            for (int mf = 0; mf < 4; mf++)
#pragma unroll
                for (int nf = 0; nf < 4; nf++)
                    mma16816(acc[mf][nf], a[mf], b[nf]);
        }
        __syncthreads();
    }

    // epilogue: scatter to Q (scaled), K, V(transposed) as fp16
#pragma unroll
    for (int mf = 0; mf < 4; mf++) {
#pragma unroll
        for (int nf = 0; nf < 4; nf++) {
            int row0 = bm * 128 + wm + mf * 16 + gid;
            int col = bn * 128 + wn + nf * 8 + tg * 2;
            int which = col >> 10, cn = col & 1023;
            const float* bias = (which == 0) ? bq : ((which == 1) ? bk : bv);
            float b0 = __ldg(&bias[cn]), b1 = __ldg(&bias[cn + 1]);
            int n = cn >> 6, d = cn & 63;
#pragma unroll
            for (int p = 0; p < 2; p++) {
                int r = row0 + p * 8;
                float v0 = acc[mf][nf][p * 2 + 0] + b0;
                float v1 = acc[mf][nf][p * 2 + 1] + b1;
                if (which == 0) { v0 *= CQ; v1 *= CQ; }
                int b = r >> 11, s = r & 2047;
                int bh = b * H + n;
                if (which == 2) {
                    g_V[(size_t)(bh * D + d) * Ss + s]     = __float2half_rn(v0);
                    g_V[(size_t)(bh * D + d + 1) * Ss + s] = __float2half_rn(v1);
                } else {
                    __half* dst = ((which == 0) ? g_Q : g_K) + ((size_t)bh * Ss + s) * D + d;
                    *reinterpret_cast<__half2*>(dst) =
                        __halves2half2(__float2half_rn(v0), __float2half_rn(v1));
                }
            }
        }
    }
}

// ---------------- flash attention (non-causal, full softmax) ----------------
// grid (Ss/128, B*H); 8 warps; each warp owns 16 query rows; key tiles of 64
__global__ __launch_bounds__(256) void flash() {
    __shared__ __half Ks[64][72];  // [key][d], pad -> conflict-free frag loads
    __shared__ __half Vs[64][72];  // [d][key]
    int tid = threadIdx.x;
    int qb = blockIdx.x, bh = blockIdx.y;
    int wid = tid >> 5, lane = tid & 31, gid = lane >> 2, tg = lane & 3;
    int q0 = qb * 128 + wid * 16;
    const __half* Qp = g_Q + (size_t)bh * Ss * D;
    const __half* Kp = g_K + (size_t)bh * Ss * D;
    const __half* Vp = g_V + (size_t)bh * D * Ss;

    // Q fragments (held in registers for the whole CTA lifetime)
    unsigned qa[4][4];
#pragma unroll
    for (int kf = 0; kf < 4; kf++) {
        int c = kf * 16 + tg * 2;
        qa[kf][0] = *(const unsigned*)&Qp[(size_t)(q0 + gid) * D + c];
        qa[kf][1] = *(const unsigned*)&Qp[(size_t)(q0 + gid + 8) * D + c];
        qa[kf][2] = *(const unsigned*)&Qp[(size_t)(q0 + gid) * D + c + 8];
        qa[kf][3] = *(const unsigned*)&Qp[(size_t)(q0 + gid + 8) * D + c + 8];
    }

    float o[8][4] = {};
    float m0 = -CUDART_INF_F, m1 = -CUDART_INF_F, l0 = 0.f, l1 = 0.f;
    int lr = tid >> 3, lc = (tid & 7) * 8;

    for (int kt = 0; kt < Ss / 64; kt++) {
        *(uint4*)&Ks[lr][lc]      = *(const uint4*)&Kp[(size_t)(kt * 64 + lr) * D + lc];
        *(uint4*)&Ks[lr + 32][lc] = *(const uint4*)&Kp[(size_t)(kt * 64 + lr + 32) * D + lc];
        *(uint4*)&Vs[lr][lc]      = *(const uint4*)&Vp[(size_t)lr * Ss + kt * 64 + lc];
        *(uint4*)&Vs[lr + 32][lc] = *(const uint4*)&Vp[(size_t)(lr + 32) * Ss + kt * 64 + lc];
        __syncthreads();

        // S = Q @ K^T  (already includes 1/sqrt(D)*log2e via Q scaling)
        float s[8][4] = {};
#pragma unroll
        for (int kf = 0; kf < 4; kf++)
#pragma unroll
            for (int nf = 0; nf < 8; nf++) {
                unsigned b2[2];
                b2[0] = *(unsigned*)&Ks[nf * 8 + gid][kf * 16 + tg * 2];
                b2[1] = *(unsigned*)&Ks[nf * 8 + gid][kf * 16 + tg * 2 + 8];
                mma16816(s[nf], qa[kf], b2);
            }

        // online softmax (rows gid and gid+8; quad = lanes {xor 1, xor 2})
        float tm0 = -CUDART_INF_F, tm1 = -CUDART_INF_F;
#pragma unroll
        for (int nf = 0; nf < 8; nf++) {
            tm0 = fmaxf(tm0, fmaxf(s[nf][0], s[nf][1]));
            tm1 = fmaxf(tm1, fmaxf(s[nf][2], s[nf][3]));
        }
        tm0 = fmaxf(tm0, __shfl_xor_sync(0xffffffffu, tm0, 1));
        tm0 = fmaxf(tm0, __shfl_xor_sync(0xffffffffu, tm0, 2));
        tm1 = fmaxf(tm1, __shfl_xor_sync(0xffffffffu, tm1, 1));
        tm1 = fmaxf(tm1, __shfl_xor_sync(0xffffffffu, tm1, 2));
        float nm0 = fmaxf(m0, tm0), nm1 = fmaxf(m1, tm1);
        float cc0 = exp2f(m0 - nm0), cc1 = exp2f(m1 - nm1);
        m0 = nm0; m1 = nm1;
        float ps0 = 0.f, ps1 = 0.f;
#pragma unroll
        for (int nf = 0; nf < 8; nf++) {
            s[nf][0] = exp2f(s[nf][0] - nm0);
            s[nf][1] = exp2f(s[nf][1] - nm0);
            s[nf][2] = exp2f(s[nf][2] - nm1);
            s[nf][3] = exp2f(s[nf][3] - nm1);
            ps0 += s[nf][0] + s[nf][1];
            ps1 += s[nf][2] + s[nf][3];
        }
        l0 = l0 * cc0 + ps0;
        l1 = l1 * cc1 + ps1;
#pragma unroll
        for (int nf = 0; nf < 8; nf++) {
            o[nf][0] *= cc0; o[nf][1] *= cc0;
            o[nf][2] *= cc1; o[nf][3] *= cc1;
        }

        // P (C-fragment layout) -> A fragments directly in registers
        unsigned pa[4][4];
#pragma unroll
        for (int kb = 0; kb < 4; kb++) {
            pa[kb][0] = pack2(__float2half_rn(s[2 * kb][0]), __float2half_rn(s[2 * kb][1]));
            pa[kb][1] = pack2(__float2half_rn(s[2 * kb][2]), __float2half_rn(s[2 * kb][3]));
            pa[kb][2] = pack2(__float2half_rn(s[2 * kb + 1][0]), __float2half_rn(s[2 * kb + 1][1]));
            pa[kb][3] = pack2(__float2half_rn(s[2 * kb + 1][2]), __float2half_rn(s[2 * kb + 1][3]));
        }

        // O += P @ V
#pragma unroll
        for (int kb = 0; kb < 4; kb++)
#pragma unroll
            for (int nf = 0; nf < 8; nf++) {
                unsigned b2[2];
                b2[0] = *(unsigned*)&Vs[nf * 8 + gid][kb * 16 + tg * 2];
                b2[1] = *(unsigned*)&Vs[nf * 8 + gid][kb * 16 + tg * 2 + 8];
                mma16816(o[nf], pa[kb], b2);
            }
        __syncthreads();
    }

    // finalize: divide by row sums, write fp16 to g_A [b*S+s][h*64+d]
    l0 += __shfl_xor_sync(0xffffffffu, l0, 1);
    l0 += __shfl_xor_sync(0xffffffffu, l0, 2);
    l1 += __shfl_xor_sync(0xffffffffu, l1, 1);
    l1 += __shfl_xor_sync(0xffffffffu, l1, 2);
    float i0 = 1.f / l0, i1 = 1.f / l1;
    int b = bh >> 4, hh = bh & 15;
    int s0 = q0 + gid;
#pragma unroll
    for (int nf = 0; nf < 8; nf++) {
        int col = hh * 64 + nf * 8 + tg * 2;
        *(__half2*)&g_A[(size_t)(b * Ss + s0) * E + col] =
            __halves2half2(__float2half_rn(o[nf][0] * i0), __float2half_rn(o[nf][1] * i0));
        *(__half2*)&g_A[(size_t)(b * Ss + s0 + 8) * E + col] =
            __halves2half2(__float2half_rn(o[nf][2] * i1), __float2half_rn(o[nf][3] * i1));
    }
}

// ---------------- output projection: [8192,1024] x [1024,1024] + bo ----------------
__global__ __launch_bounds__(256) void gemm_o(const float* __restrict__ bo,
                                              float* __restrict__ out) {
    constexpr int K = E, Nn = E;
    __shared__ __half As[128][40];
    __shared__ __half Bs[32][136];
    int tid = threadIdx.x;
    int bn = blockIdx.x, bm = blockIdx.y;
    int wid = tid >> 5, lane = tid & 31;
    int gid = lane >> 2, tg = lane & 3;
    int wm = (wid >> 2) * 64, wn = (wid & 3) * 32;
    float acc[4][4][4] = {};
    const __half* Ag = g_A + (size_t)bm * 128 * K;
    const __half* Bg = g_Wo + bn * 128;
    int ar = tid >> 2, ac = (tid & 3) * 8;
    int br = tid >> 4, bc = (tid & 15) * 8;

    for (int kt = 0; kt < K / 32; kt++) {
        *(uint4*)&As[ar][ac]      = *(const uint4*)&Ag[(size_t)ar * K + kt * 32 + ac];
        *(uint4*)&As[ar + 64][ac] = *(const uint4*)&Ag[(size_t)(ar + 64) * K + kt * 32 + ac];
        *(uint4*)&Bs[br][bc]      = *(const uint4*)&Bg[(size_t)(kt * 32 + br) * Nn + bc];
        *(uint4*)&Bs[br + 16][bc] = *(const uint4*)&Bg[(size_t)(kt * 32 + br + 16) * Nn + bc];
        __syncthreads();
#pragma unroll
        for (int ks = 0; ks < 2; ks++) {
            unsigned a[4][4], b[4][2];
#pragma unroll
            for (int mf = 0; mf < 4; mf++) {
                int r = wm + mf * 16 + gid, c = ks * 16 + tg * 2;
                a[mf][0] = *(unsigned*)&As[r][c];
                a[mf][1] = *(unsigned*)&As[r + 8][c];
                a[mf][2] = *(unsigned*)&As[r][c + 8];
                a[mf][3] = *(unsigned*)&As[r + 8][c + 8];
            }
#pragma unroll
            for (int nf = 0; nf < 4; nf++) {
                int c = wn + nf * 8 + gid, k0 = ks * 16 + tg * 2;
                b[nf][0] = pack2(Bs[k0][c], Bs[k0 + 1][c]);
                b[nf][1] = pack2(Bs[k0 + 8][c], Bs[k0 + 9][c]);
            }
#pragma unroll
            for (int mf = 0; mf < 4; mf++)
#pragma unroll
                for (int nf = 0; nf < 4; nf++)
                    mma16816(acc[mf][nf], a[mf], b[nf]);
        }
        __syncthreads();
    }

#pragma unroll
    for (int mf = 0; mf < 4; mf++) {
#pragma unroll
        for (int nf = 0; nf < 4; nf++) {
            int row0 = bm * 128 + wm + mf * 16 + gid;
            int col = bn * 128 + wn + nf * 8 + tg * 2;
            float b0 = __ldg(&bo[col]), b1 = __ldg(&bo[col + 1]);
            *(float2*)&out[(size_t)row0 * E + col] =
                make_float2(acc[mf][nf][0] + b0, acc[mf][nf][1] + b1);
            *(float2*)&out[(size_t)(row0 + 8) * E + col] =
                make_float2(acc[mf][nf][2] + b0, acc[mf][nf][3] + b1);
        }
    }
}

// ---------------- launch ----------------
extern "C" void kernel_launch(void* const* d_in, const int* in_sizes, int n_in,
                              void* d_out, int out_size) {
    const float* x  = (const float*)d_in[0];
    const float* Wq = (const float*)d_in[1];
    const float* bq = (const float*)d_in[2];
    const float* Wk = (const float*)d_in[3];
    const float* bk = (const float*)d_in[4];
    const float* Wv = (const float*)d_in[5];
    const float* bv = (const float*)d_in[6];
    const float* Wo = (const float*)d_in[7];
    const float* bo = (const float*)d_in[8];
    float* out = (float*)d_out;

    pack_x<<<(M * E) / 256, 256>>>(x);
    pack_wqkv<<<(E * N_QKV) / 256, 256>>>(Wq, Wk, Wv);
    pack_wo<<<(E * E) / 256, 256>>>(Wo);
    gemm_qkv<<<dim3(N_QKV / 128, M / 128), 256>>>(bq, bk, bv);
    flash<<<dim3(Ss / 128, Bb * H), 256>>>();
    gemm_o<<<dim3(E / 128, M / 128), 256>>>(bo, out);
}